// round 12
// baseline (speedup 1.0000x reference)
#include <cuda_runtime.h>
#include <cstdint>

#define T_STEPS 256
#define BATCH   128
#define KDIM    1536
#define F4      384     // KDIM/4 (float4 units)
#define NTHR    128
#define STAGES  4
#define STAGE_B 6144u   // F4 * 16 bytes

// HW tanh: single MUFU op, max rel err ~2^-11.
__device__ __forceinline__ float tanha(float x) {
    float y;
    asm("tanh.approx.f32 %0, %1;" : "=f"(y) : "f"(x));
    return y;
}

__device__ __forceinline__ void cp_async16(uint32_t dst, const void* src) {
    asm volatile("cp.async.cg.shared.global [%0], [%1], 16;" :: "r"(dst), "l"(src));
}
#define CP_COMMIT() asm volatile("cp.async.commit_group;" ::: "memory")
#define CP_WAIT2()  asm volatile("cp.async.wait_group 2;" ::: "memory")

// packed f32x2 fma
__device__ __forceinline__ void ffma2(unsigned long long& acc,
                                      unsigned long long a,
                                      unsigned long long b) {
    asm("fma.rn.f32x2 %0, %1, %2, %0;" : "+l"(acc) : "l"(a), "l"(b));
}
__device__ __forceinline__ float2 unpack2(unsigned long long v) {
    float2 f;
    asm("mov.b64 {%0, %1}, %2;" : "=f"(f.x), "=f"(f.y) : "l"(v));
    return f;
}

// 12-term dot product (3 float4 each side), 2 accumulator chains.
__device__ __forceinline__ float dot12(const float4* v, const float4* w) {
    float a0 = 0.0f, a1 = 0.0f;
    #pragma unroll
    for (int j = 0; j < 3; j++) {
        a0 = fmaf(v[j].x, w[j].x, fmaf(v[j].y, w[j].y, a0));
        a1 = fmaf(v[j].z, w[j].z, fmaf(v[j].w, w[j].w, a1));
    }
    return a0 + a1;
}

// ---------------------------------------------------------------------------
// One CTA per batch element, 128 threads (4 warps). Strided float4 ownership
// (tid + 128*j): fully coalesced. 4-stage cp.async input ring, unrolled by 4
// (static stages / parity / SMEM addresses), strength-reduced gmem pointers.
// Per step: 6-sum butterfly cut to THREE shfl levels (xor16/8/4) — each warp
// then holds 4 disjoint 8-lane partials per sum; 24 writer lanes store them
// to 16-wide rows (one predicated STS), one barrier, 16-wide tail reduce
// (4 independent LDS.128 + add tree), 6 broadcasts, tanh.approx update.
// ---------------------------------------------------------------------------
__global__ void __launch_bounds__(NTHR) fused_kernel(
    const float* __restrict__ inputs,
    const float* __restrict__ h0,
    const float* __restrict__ c0,
    const float* __restrict__ Wr,
    const float* __restrict__ br,
    const float* __restrict__ Wc,
    const float* __restrict__ bc,
    const float* __restrict__ Wi,
    const float* __restrict__ bi,
    float* __restrict__ out)
{
    __shared__ float      sPart[2][8][16];    // [buf][row][16 partials]
    __shared__ ulonglong2 sX[STAGES * F4];    // 4 x 6KB input stages (packed)

    const int tid  = threadIdx.x;
    const int b    = blockIdx.x;
    const int warp = tid >> 5;
    const int lane = tid & 31;

    const float4*     in4  = (const float4*)inputs;
    const float4*     Wr4  = (const float4*)Wr;
    const float4*     Wc4  = (const float4*)Wc;
    const ulonglong2* Wi2  = (const ulonglong2*)Wi;
    float4* out4 = (float4*)out;

    float4 h[3], c[3], wr0[3], wr1[3], wc0[3], wc1[3];
    ulonglong2 wi0p[3], wi1p[3];
    #pragma unroll
    for (int j = 0; j < 3; j++) {
        const int p = tid + 128 * j;           // strided ownership: coalesced
        h[j]    = ((const float4*)h0)[b * F4 + p];
        c[j]    = ((const float4*)c0)[b * F4 + p];
        wr0[j]  = Wr4[p];        wr1[j]  = Wr4[F4 + p];
        wc0[j]  = Wc4[p];        wc1[j]  = Wc4[F4 + p];
        wi0p[j] = Wi2[p];        wi1p[j] = Wi2[F4 + p];
    }
    const float br0 = br[0], br1 = br[1];
    const float bc0 = bc[0], bc1 = bc[1];
    const float bi0 = bi[0], bi1 = bi[1];

    const int rid = lane & 7;
    const float mybias = (rid == 0) ? br0 : (rid == 1) ? br1
                       : (rid == 2) ? bc0 : (rid == 3) ? bc1
                       : (rid == 4) ? bi0 : (rid == 5) ? bi1 : 0.0f;

    // lane roles
    const bool lo  = lane < 16;
    const bool b3  = (lane & 8) != 0;
    const bool b2  = (lane & 4) != 0;
    // 3-level butterfly writers: lo lanes hold g(lane>>2) partial (class lane&3);
    // hi lanes 16-19 hold x4 partials, 24-27 x5 (20-23 / 28-31 duplicates -> idle)
    const bool writer = lo || ((lane & 7) < 4);
    const int  wrow   = lo ? (lane >> 2) : (4 + ((lane >> 3) & 1));
    const int  wcol   = warp * 4 + (lane & 3);

    // zero ALL of sPart once (rows 6,7 stay zero; prologue rows get clean pad)
    {
        float2* sp2 = (float2*)&sPart[0][0][0];
        sp2[tid] = make_float2(0.0f, 0.0f);    // 128 threads x 2 = 256 floats
    }
    __syncthreads();

    const uint32_t sx_tid =
        (uint32_t)__cvta_generic_to_shared(&sX[0]) + (uint32_t)tid * 16u;
    const ulonglong2* sXu = &sX[0];

    // ---- prologue: X0 projection; fill stages 1..3 with x_1..x_3 ----
    {
        float4 x0[3];
        #pragma unroll
        for (int j = 0; j < 3; j++)
            x0[j] = in4[(long)b * F4 + tid + 128 * j];
        float4 wi0f[3], wi1f[3];
        #pragma unroll
        for (int j = 0; j < 3; j++) {
            wi0f[j] = *(const float4*)&wi0p[j];
            wi1f[j] = *(const float4*)&wi1p[j];
        }
        float v4 = dot12(x0, wi0f);
        float v5 = dot12(x0, wi1f);

        #pragma unroll
        for (int s = 1; s <= 3; s++) {
            const float4* src = in4 + (long)s * BATCH * F4 + (long)b * F4 + tid;
            const uint32_t dst = sx_tid + (uint32_t)s * STAGE_B;
            cp_async16(dst,         src);
            cp_async16(dst + 2048u, src + 128);
            cp_async16(dst + 4096u, src + 256);
            CP_COMMIT();
        }

        // full 5-level reduce for prologue (one-time); lane0/16 write single
        // partial into col warp*4 (other 3 cols are zero from the memset)
        float k  = lo ? v4 : v5;
        float s_ = lo ? v5 : v4;
        k += __shfl_xor_sync(~0u, s_, 16);
        k += __shfl_xor_sync(~0u, k, 8);
        k += __shfl_xor_sync(~0u, k, 4);
        k += __shfl_xor_sync(~0u, k, 2);
        k += __shfl_xor_sync(~0u, k, 1);
        if (lane == 0)  sPart[1][4][warp * 4] = k;
        if (lane == 16) sPart[1][5][warp * 4] = k;
    }
    __syncthreads();
    float Xc, Xh;
    {
        const float4* r4 = (const float4*)sPart[1][4];
        const float4* r5 = (const float4*)sPart[1][5];
        float4 a0 = r4[0], a1 = r4[1], a2 = r4[2], a3 = r4[3];
        float4 d0 = r5[0], d1 = r5[1], d2 = r5[2], d3 = r5[3];
        Xc = (((a0.x + a0.y) + (a0.z + a0.w)) + ((a1.x + a1.y) + (a1.z + a1.w)))
           + (((a2.x + a2.y) + (a2.z + a2.w)) + ((a3.x + a3.y) + (a3.z + a3.w))) + bi0;
        Xh = (((d0.x + d0.y) + (d0.z + d0.w)) + ((d1.x + d1.y) + (d1.z + d1.w)))
           + (((d2.x + d2.y) + (d2.z + d2.w)) + ((d3.x + d3.y) + (d3.z + d3.w))) + bi1;
    }

    // strength-reduced pointers
    const float4* srcp = in4 + (long)4 * BATCH * F4 + (long)b * F4 + tid; // x_{t+4}
    float4*       outp = out4 + (long)b * F4 + tid;

#define DO_STEP(SC, SW, BUF, SRC)                                              \
    {                                                                          \
        CP_WAIT2();                                                            \
        const ulonglong2* xs = sXu + (SC) * F4 + tid;                          \
        ulonglong2 x0 = xs[0], x1 = xs[128], x2 = xs[256];                     \
        {   /* refill stage SW with x from SRC */                              \
            const uint32_t dst = sx_tid + (uint32_t)(SW) * STAGE_B;            \
            cp_async16(dst,         (SRC));                                    \
            cp_async16(dst + 2048u, (SRC) + 128);                              \
            cp_async16(dst + 4096u, (SRC) + 256);                              \
            CP_COMMIT();                                                       \
        }                                                                      \
        /* x-projection dots for t+1: packed FFMA2 */                          \
        unsigned long long a0 = 0ull, a1 = 0ull, q0_ = 0ull, q1_ = 0ull;       \
        ffma2(a0, x0.x, wi0p[0].x); ffma2(a1, x0.y, wi0p[0].y);                \
        ffma2(q0_, x0.x, wi1p[0].x); ffma2(q1_, x0.y, wi1p[0].y);              \
        ffma2(a0, x1.x, wi0p[1].x); ffma2(a1, x1.y, wi0p[1].y);                \
        ffma2(q0_, x1.x, wi1p[1].x); ffma2(q1_, x1.y, wi1p[1].y);              \
        ffma2(a0, x2.x, wi0p[2].x); ffma2(a1, x2.y, wi0p[2].y);                \
        ffma2(q0_, x2.x, wi1p[2].x); ffma2(q1_, x2.y, wi1p[2].y);              \
        float2 pa0 = unpack2(a0), pa1 = unpack2(a1);                           \
        float2 pb0 = unpack2(q0_), pb1 = unpack2(q1_);                         \
        float x4 = (pa0.x + pa0.y) + (pa1.x + pa1.y);                          \
        float x5 = (pb0.x + pb0.y) + (pb1.x + pb1.y);                          \
        /* gate dots */                                                        \
        float g0 = dot12(h, wr0), g1 = dot12(h, wr1);                          \
        float g2 = dot12(c, wc0), g3 = dot12(c, wc1);                          \
        /* 6-sum butterfly: THREE levels only (xor16/8/4) */                   \
        float rA = __shfl_xor_sync(~0u, lo ? x4 : g0, 16);                     \
        float rB = __shfl_xor_sync(~0u, lo ? x5 : g1, 16);                     \
        float rC = __shfl_xor_sync(~0u, g2, 16);                               \
        float rD = __shfl_xor_sync(~0u, g3, 16);                               \
        if (lo) { g0 += rA; g1 += rB; g2 += rC; g3 += rD; }                    \
        else    { x4 += rA; x5 += rB; }                                        \
        float P  = lo ? (b3 ? g2 : g0) : (b3 ? x5 : x4);                       \
        float sP = lo ? (b3 ? g0 : g2) : (b3 ? x4 : x5);                       \
        P += __shfl_xor_sync(~0u, sP, 8);                                      \
        float Q  = b3 ? g3 : g1;                                               \
        float sQ = b3 ? g1 : g3;                                               \
        Q += __shfl_xor_sync(~0u, sQ, 8);                                      \
        float R  = lo ? (b2 ? Q : P) : P;                                      \
        float sR = lo ? (b2 ? P : Q) : P;                                      \
        R += __shfl_xor_sync(~0u, sR, 4);                                      \
        /* each writer lane holds one disjoint 8-lane partial */               \
        if (writer) sPart[BUF][wrow][wcol] = R;                                \
        __syncthreads();                                                       \
        /* tail: 16 cross-warp partials of row rid (4 independent LDS.128) */  \
        const float4* rp = (const float4*)sPart[BUF][rid];                     \
        float4 t0 = rp[0], t1 = rp[1], t2 = rp[2], t3 = rp[3];                 \
        float s = ((((t0.x + t0.y) + (t0.z + t0.w))                            \
                  + ((t1.x + t1.y) + (t1.z + t1.w)))                           \
                 + (((t2.x + t2.y) + (t2.z + t2.w))                            \
                  + ((t3.x + t3.y) + (t3.z + t3.w)))) + mybias;                \
        float gval;                                                            \
        if (rid < 4) {                                                         \
            float sg  = fmaf(-0.5f, tanha(0.5f * s), 0.5f);                    \
            float fac = (rid == 0) ? Xc : (rid == 3) ? Xh : 1.0f;              \
            gval = sg * fac;                                                   \
        } else {                                                               \
            gval = s;                                                          \
        }                                                                      \
        const float gca = __shfl_sync(~0u, gval, 0);                           \
        const float ghb = __shfl_sync(~0u, gval, 1);                           \
        const float gcb = __shfl_sync(~0u, gval, 2);                           \
        const float gha = __shfl_sync(~0u, gval, 3);                           \
        Xc = __shfl_sync(~0u, gval, 4);                                        \
        Xh = __shfl_sync(~0u, gval, 5);                                        \
        _Pragma("unroll")                                                      \
        for (int j = 0; j < 3; j++) {                                          \
            h[j].x = tanha(fmaf(ghb, h[j].x, gha));                            \
            h[j].y = tanha(fmaf(ghb, h[j].y, gha));                            \
            h[j].z = tanha(fmaf(ghb, h[j].z, gha));                            \
            h[j].w = tanha(fmaf(ghb, h[j].w, gha));                            \
            c[j].x = tanha(fmaf(gcb, c[j].x, gca));                            \
            c[j].y = tanha(fmaf(gcb, c[j].y, gca));                            \
            c[j].z = tanha(fmaf(gcb, c[j].z, gca));                            \
            c[j].w = tanha(fmaf(gcb, c[j].w, gca));                            \
            outp[128 * j] = h[j];                                              \
        }                                                                      \
        outp += BATCH * F4;                                                    \
    }

    // main loop: 252 steps, unrolled by 4 (static stages / buffer parity)
    for (int tb = 0; tb < 252; tb += 4) {
        DO_STEP(1, 0, 0, srcp); srcp += BATCH * F4;
        DO_STEP(2, 1, 1, srcp); srcp += BATCH * F4;
        DO_STEP(3, 2, 0, srcp); srcp += BATCH * F4;
        DO_STEP(0, 3, 1, srcp); srcp += BATCH * F4;
    }
    // tail: steps 252..255, refill source clamped to x_255
    {
        const float4* srcL = in4 + (long)(T_STEPS - 1) * BATCH * F4
                           + (long)b * F4 + tid;
        DO_STEP(1, 0, 0, srcL);
        DO_STEP(2, 1, 1, srcL);
        DO_STEP(3, 2, 0, srcL);
        DO_STEP(0, 3, 1, srcL);
    }
#undef DO_STEP

    // final hT, cT
    const long offH = (long)T_STEPS * BATCH * F4;
    const long offC = offH + (long)BATCH * F4;
    #pragma unroll
    for (int j = 0; j < 3; j++) {
        out4[offH + (long)b * F4 + tid + 128 * j] = h[j];
        out4[offC + (long)b * F4 + tid + 128 * j] = c[j];
    }
}

extern "C" void kernel_launch(void* const* d_in, const int* in_sizes, int n_in,
                              void* d_out, int out_size)
{
    const float* inputs = (const float*)d_in[0];
    const float* h0     = (const float*)d_in[1];
    const float* c0     = (const float*)d_in[2];
    const float* Wr     = (const float*)d_in[3];
    const float* br     = (const float*)d_in[4];
    const float* Wc     = (const float*)d_in[5];
    const float* bc     = (const float*)d_in[6];
    const float* Wi     = (const float*)d_in[7];
    const float* bi     = (const float*)d_in[8];
    float* out = (float*)d_out;

    fused_kernel<<<BATCH, NTHR>>>(inputs, h0, c0, Wr, br, Wc, bc, Wi, bi, out);
}

// round 13
// speedup vs baseline: 1.9093x; 1.9093x over previous
#include <cuda_runtime.h>
#include <cstdint>

#define T_STEPS 256
#define BATCH   128
#define KDIM    1536
#define F4      384     // KDIM/4 (float4 units)
#define NTHR    256     // 8 warps: 0-3 = h-half, 4-7 = c-half
#define STAGE_B 6144u   // F4 * 16 bytes

// HW tanh: single MUFU op, max rel err ~2^-11.
__device__ __forceinline__ float tanha(float x) {
    float y;
    asm("tanh.approx.f32 %0, %1;" : "=f"(y) : "f"(x));
    return y;
}

__device__ __forceinline__ void cp_async16(uint32_t dst, const void* src) {
    asm volatile("cp.async.cg.shared.global [%0], [%1], 16;" :: "r"(dst), "l"(src));
}
#define CP_COMMIT() asm volatile("cp.async.commit_group;" ::: "memory")
#define CP_WAIT2()  asm volatile("cp.async.wait_group 2;" ::: "memory")

// packed f32x2 fma
__device__ __forceinline__ void ffma2(unsigned long long& acc,
                                      unsigned long long a,
                                      unsigned long long b) {
    asm("fma.rn.f32x2 %0, %1, %2, %0;" : "+l"(acc) : "l"(a), "l"(b));
}
__device__ __forceinline__ float2 unpack2(unsigned long long v) {
    float2 f;
    asm("mov.b64 {%0, %1}, %2;" : "=f"(f.x), "=f"(f.y) : "l"(v));
    return f;
}

// 12-term dot product (3 float4 each side), 2 accumulator chains.
__device__ __forceinline__ float dot12(const float4* v, const float4* w) {
    float a0 = 0.0f, a1 = 0.0f;
    #pragma unroll
    for (int j = 0; j < 3; j++) {
        a0 = fmaf(v[j].x, w[j].x, fmaf(v[j].y, w[j].y, a0));
        a1 = fmaf(v[j].z, w[j].z, fmaf(v[j].w, w[j].w, a1));
    }
    return a0 + a1;
}

// ---------------------------------------------------------------------------
// One CTA per batch, 256 threads. Warps 0-3 own the h-state (full 1536 dims,
// htid = tid&127 strided float4 slots), warps 4-7 own the c-state. Each half
// computes its 2 gate dots + 1 input-projection sum -> 3-sum butterfly in
// 6 SHFLs. One barrier/step; 4-wide tail identical to the 109us kernel.
// x is consumed from registers loaded (post-barrier) from a 4-stage cp.async
// ring refilled by h-warps only. c-warps do no STG in the loop.
// ---------------------------------------------------------------------------
__global__ void __launch_bounds__(NTHR) fused_kernel(
    const float* __restrict__ inputs,
    const float* __restrict__ h0,
    const float* __restrict__ c0,
    const float* __restrict__ Wr,
    const float* __restrict__ br,
    const float* __restrict__ Wc,
    const float* __restrict__ bc,
    const float* __restrict__ Wi,
    const float* __restrict__ bi,
    float* __restrict__ out)
{
    __shared__ float      sPart[2][8][4];   // [buf][row][warp&3]; rows 0-5 used
    __shared__ ulonglong2 sX[4 * F4];       // 4 x 6KB input stages (packed)

    const int tid   = threadIdx.x;
    const int b     = blockIdx.x;
    const int warp  = tid >> 5;
    const int lane  = tid & 31;
    const int htid  = tid & 127;
    const bool isH  = warp < 4;

    const float4*     in4  = (const float4*)inputs;
    const ulonglong2* in2u = (const ulonglong2*)inputs;
    const ulonglong2* Wi2  = (const ulonglong2*)Wi;
    float4* out4 = (float4*)out;

    // state + weights for this half
    float4 st[3], w0[3], w1[3];
    ulonglong2 wip[3];
    {
        const float4* st0 = isH ? (const float4*)h0 : (const float4*)c0;
        const float4* Wg  = isH ? (const float4*)Wr : (const float4*)Wc;
        const ulonglong2* Wx = isH ? Wi2 : (Wi2 + F4);
        #pragma unroll
        for (int j = 0; j < 3; j++) {
            const int p = htid + 128 * j;
            st[j]  = st0[b * F4 + p];
            w0[j]  = Wg[p];
            w1[j]  = Wg[F4 + p];
            wip[j] = Wx[p];
        }
    }
    const float br0 = br[0], br1 = br[1];
    const float bc0 = bc[0], bc1 = bc[1];
    const float bi0 = bi[0], bi1 = bi[1];

    const int rid = lane & 7;
    const float mybias = (rid == 0) ? br0 : (rid == 1) ? br1
                       : (rid == 2) ? bc0 : (rid == 3) ? bc1
                       : (rid == 4) ? bi0 : (rid == 5) ? bi1 : 0.0f;

    // butterfly lane roles (3 sums per warp)
    const bool lo  = lane < 16;
    const bool b3  = (lane & 8) != 0;
    const bool writer = (lane == 0) || (lane == 8) || (lane == 16);
    const int  base = isH ? 0 : 2;              // gate rows: h->0,1  c->2,3
    const int  xrow = isH ? 4 : 5;              // x rows:   h->4    c->5
    const int  wrow = (lane == 16) ? xrow : base + (lane >> 3);
    const int  wcol = warp & 3;

    // zero unused tail rows (6,7) in both buffers
    if (tid < 16) {
        const int bf = tid >> 3, r = 6 + ((tid >> 2) & 1), col = tid & 3;
        sPart[bf][r][col] = 0.0f;
    }

    const uint32_t sx_tid =
        (uint32_t)__cvta_generic_to_shared(&sX[0]) + (uint32_t)htid * 16u;
    const ulonglong2* sXu = &sX[0];

    // ---- prologue: X0 projection; xreg=x_1; stages 2,3,0,1 <- x_2..x_5 ----
    ulonglong2 xr[3];
    {
        float4 x0[3], wif[3];
        #pragma unroll
        for (int j = 0; j < 3; j++) {
            x0[j]  = in4[(long)b * F4 + htid + 128 * j];
            wif[j] = *(const float4*)&wip[j];
            xr[j]  = in2u[(long)(1 * BATCH + b) * F4 + htid + 128 * j]; // x_1
        }
        float v = dot12(x0, wif);   // h-half: x.wi0 ; c-half: x.wi1

        if (isH) {
            #pragma unroll
            for (int s = 2; s <= 5; s++) {
                const float4* src = in4 + (long)s * BATCH * F4 + (long)b * F4 + htid;
                const uint32_t dst = sx_tid + (uint32_t)(s & 3) * STAGE_B;
                cp_async16(dst,         src);
                cp_async16(dst + 2048u, src + 128);
                cp_async16(dst + 4096u, src + 256);
                CP_COMMIT();
            }
        }

        // full warp reduce of v
        v += __shfl_xor_sync(~0u, v, 16);
        v += __shfl_xor_sync(~0u, v, 8);
        v += __shfl_xor_sync(~0u, v, 4);
        v += __shfl_xor_sync(~0u, v, 2);
        v += __shfl_xor_sync(~0u, v, 1);
        if (lane == 0) sPart[1][xrow][wcol] = v;
    }
    __syncthreads();
    float Xc, Xh;
    {
        float4 q4 = *(const float4*)sPart[1][4];
        float4 q5 = *(const float4*)sPart[1][5];
        Xc = (q4.x + q4.y) + (q4.z + q4.w) + bi0;
        Xh = (q5.x + q5.y) + (q5.z + q5.w) + bi1;
    }

    // strength-reduced pointers
    const float4* srcp = in4 + (long)6 * BATCH * F4 + (long)b * F4 + htid; // x_{t+6}
    float4*       outp = out4 + (long)b * F4 + htid;

#define DO_STEP(SC2, BUF, SRC)                                                 \
    {                                                                          \
        /* gate dots for this half */                                          \
        float g0 = dot12(st, w0), g1 = dot12(st, w1);                          \
        /* x-projection (x_{t+1}) via packed FFMA2 */                          \
        unsigned long long a0 = 0ull, a1 = 0ull;                               \
        ffma2(a0, xr[0].x, wip[0].x); ffma2(a1, xr[0].y, wip[0].y);            \
        ffma2(a0, xr[1].x, wip[1].x); ffma2(a1, xr[1].y, wip[1].y);            \
        ffma2(a0, xr[2].x, wip[2].x); ffma2(a1, xr[2].y, wip[2].y);            \
        float2 pa = unpack2(a0), pb = unpack2(a1);                             \
        float C = (pa.x + pa.y) + (pb.x + pb.y);                               \
        /* 3-sum butterfly: 6 SHFL, 5 levels */                                \
        float rA = __shfl_xor_sync(~0u, lo ? C : g0, 16);                      \
        float rB = __shfl_xor_sync(~0u, g1, 16);                               \
        if (lo) { g0 += rA; g1 += rB; } else { C += rA; }                      \
        float keep = b3 ? g1 : g0;                                             \
        float send = b3 ? g0 : g1;                                             \
        float v2 = lo ? send : C;                                              \
        float r2 = __shfl_xor_sync(~0u, v2, 8);                                \
        float R  = lo ? (keep + r2) : (C + r2);                                \
        R += __shfl_xor_sync(~0u, R, 4);                                       \
        R += __shfl_xor_sync(~0u, R, 2);                                       \
        R += __shfl_xor_sync(~0u, R, 1);                                       \
        if (writer) sPart[BUF][wrow][wcol] = R;                                \
        CP_WAIT2();                                                            \
        __syncthreads();                                                       \
        /* tail: 4 cross-warp partials of row rid */                           \
        float4 qv = *(const float4*)sPart[BUF][rid];                           \
        float s = (qv.x + qv.y) + (qv.z + qv.w) + mybias;                      \
        float gval;                                                            \
        if (rid < 4) {                                                         \
            float sg  = fmaf(-0.5f, tanha(0.5f * s), 0.5f);                    \
            float fac = (rid == 0) ? Xc : (rid == 3) ? Xh : 1.0f;              \
            gval = sg * fac;                                                   \
        } else {                                                               \
            gval = s;                                                          \
        }                                                                      \
        const float gca = __shfl_sync(~0u, gval, 0);                           \
        const float ghb = __shfl_sync(~0u, gval, 1);                           \
        const float gcb = __shfl_sync(~0u, gval, 2);                           \
        const float gha = __shfl_sync(~0u, gval, 3);                           \
        Xc = __shfl_sync(~0u, gval, 4);                                        \
        Xh = __shfl_sync(~0u, gval, 5);                                        \
        const float ga = isH ? gha : gca;                                      \
        const float gb = isH ? ghb : gcb;                                      \
        /* epilogue: next xreg from stage SC2; h-warps refill it */            \
        {                                                                      \
            const ulonglong2* xs = sXu + (SC2) * F4 + htid;                    \
            xr[0] = xs[0]; xr[1] = xs[128]; xr[2] = xs[256];                   \
        }                                                                      \
        if (isH) {                                                             \
            const uint32_t dst = sx_tid + (uint32_t)(SC2) * STAGE_B;           \
            cp_async16(dst,         (SRC));                                    \
            cp_async16(dst + 2048u, (SRC) + 128);                              \
            cp_async16(dst + 4096u, (SRC) + 256);                              \
            CP_COMMIT();                                                       \
        }                                                                      \
        /* state update */                                                     \
        _Pragma("unroll")                                                      \
        for (int j = 0; j < 3; j++) {                                          \
            st[j].x = tanha(fmaf(gb, st[j].x, ga));                            \
            st[j].y = tanha(fmaf(gb, st[j].y, ga));                            \
            st[j].z = tanha(fmaf(gb, st[j].z, ga));                            \
            st[j].w = tanha(fmaf(gb, st[j].w, ga));                            \
        }                                                                      \
        if (isH) {                                                             \
            outp[0]   = st[0];                                                 \
            outp[128] = st[1];                                                 \
            outp[256] = st[2];                                                 \
        }                                                                      \
        outp += BATCH * F4;                                                    \
    }

    // main loop: 248 steps, unrolled by 4 (static stage / parity)
    for (int tb = 0; tb < 248; tb += 4) {
        DO_STEP(2, 0, srcp); srcp += BATCH * F4;
        DO_STEP(3, 1, srcp); srcp += BATCH * F4;
        DO_STEP(0, 0, srcp); srcp += BATCH * F4;
        DO_STEP(1, 1, srcp); srcp += BATCH * F4;
    }
    // tail: steps 248..255 (x_254, x_255 real; rest clamped to x_255)
    {
        const float4* srcL = in4 + (long)(T_STEPS - 1) * BATCH * F4
                           + (long)b * F4 + htid;
        DO_STEP(2, 0, srcp); srcp += BATCH * F4;   // t=248: loads x_254
        DO_STEP(3, 1, srcp);                        // t=249: loads x_255
        DO_STEP(0, 0, srcL);                        // t=250..255: clamped
        DO_STEP(1, 1, srcL);
        DO_STEP(2, 0, srcL);
        DO_STEP(3, 1, srcL);
        DO_STEP(0, 0, srcL);
        DO_STEP(1, 1, srcL);
    }
#undef DO_STEP

    // final hT (h-warps), cT (c-warps)
    const long offH = (long)T_STEPS * BATCH * F4;
    const long offC = offH + (long)BATCH * F4;
    float4* fin = out4 + (isH ? offH : offC) + (long)b * F4 + htid;
    fin[0]   = st[0];
    fin[128] = st[1];
    fin[256] = st[2];
}

extern "C" void kernel_launch(void* const* d_in, const int* in_sizes, int n_in,
                              void* d_out, int out_size)
{
    const float* inputs = (const float*)d_in[0];
    const float* h0     = (const float*)d_in[1];
    const float* c0     = (const float*)d_in[2];
    const float* Wr     = (const float*)d_in[3];
    const float* br     = (const float*)d_in[4];
    const float* Wc     = (const float*)d_in[5];
    const float* bc     = (const float*)d_in[6];
    const float* Wi     = (const float*)d_in[7];
    const float* bi     = (const float*)d_in[8];
    float* out = (float*)d_out;

    fused_kernel<<<BATCH, NTHR>>>(inputs, h0, c0, Wr, br, Wc, bc, Wi, bi, out);
}